// round 10
// baseline (speedup 1.0000x reference)
#include <cuda_runtime.h>
#include <cuda_fp16.h>
#include <cstdint>

// ---------------------------------------------------------------------------
// complexGRUCell: B=16384, I=256, H=256, fp32 in/out.
// fp16 tensor-core GEMMs (mma.m16n8k16) + ldmatrix + 3-stage cp.async,
// CTA 128x128, 4 warps (2m x 2n), warp tile 64x64, 2 CTA/SM.
// Fused-weight output columns are re/im INTERLEAVED (col 2j=re_j, 2j+1=im_j;
// segments r|z|ph), so gate nonlinearities fuse into the GEMM epilogues:
//   GEMM1 r-segment CTAs -> sigmoid + r(*)h -> g_RHh directly
//   GEMM2 CTAs           -> z/tanh/gate-combine -> out directly
// e1/e2 kernels eliminated; C1 r-region and C2 never materialized.
// __device__ globals resolved INSIDE device code (GB300/ATS host-shadow trap).
// ---------------------------------------------------------------------------

#define B_ROWS 16384
#define HDIM   256
#define G1_N   1536
#define G1_K   1024
#define G2_N   512
#define G2_K   512

__device__ __half g_G1h[G1_N * G1_K];
__device__ __half g_G2h[G2_N * G2_K];
__device__ __half g_Ah[(size_t)B_ROWS * G1_K];
__device__ __half g_RHh[(size_t)B_ROWS * 512];
__device__ float  g_bias[G1_N];
__device__ __half g_C1h[(size_t)B_ROWS * G1_N];   // only cols [512,1536) used

// ---- PTX helpers ------------------------------------------------------------
__device__ __forceinline__ uint32_t smem_u32(const void* p) {
    uint32_t a;
    asm("{ .reg .u64 t; cvta.to.shared.u64 t, %1; cvt.u32.u64 %0, t; }"
        : "=r"(a) : "l"(p));
    return a;
}
__device__ __forceinline__ void cp16(uint32_t s, const void* g) {
    asm volatile("cp.async.cg.shared.global [%0], [%1], 16;" :: "r"(s), "l"(g));
}
__device__ __forceinline__ void cp_commit() {
    asm volatile("cp.async.commit_group;" ::: "memory");
}
__device__ __forceinline__ void cp_wait1() {
    asm volatile("cp.async.wait_group 1;" ::: "memory");
}
__device__ __forceinline__ void cp_wait0() {
    asm volatile("cp.async.wait_group 0;" ::: "memory");
}
__device__ __forceinline__ void ldsm4(uint32_t* r, uint32_t addr) {
    asm volatile("ldmatrix.sync.aligned.m8n8.x4.shared.b16 {%0,%1,%2,%3}, [%4];"
                 : "=r"(r[0]), "=r"(r[1]), "=r"(r[2]), "=r"(r[3]) : "r"(addr));
}
__device__ __forceinline__ void mma_f16(float* c, const uint32_t* a,
                                        const uint32_t* b) {
    asm volatile(
        "mma.sync.aligned.m16n8k16.row.col.f32.f16.f16.f32 "
        "{%0,%1,%2,%3}, {%4,%5,%6,%7}, {%8,%9}, {%0,%1,%2,%3};"
        : "+f"(c[0]), "+f"(c[1]), "+f"(c[2]), "+f"(c[3])
        : "r"(a[0]), "r"(a[1]), "r"(a[2]), "r"(a[3]), "r"(b[0]), "r"(b[1]));
}
__device__ __forceinline__ float sigmoidf_(float x) {
    return 1.0f / (1.0f + __expf(-x));
}

// ---- weight / activation preparation (interleaved output columns) -----------
// G1 column n: seg = n>>9 (0=r,1=z,2=ph), j = (n&511)>>1, im = n&1.
__global__ void prep_g1(const float* __restrict__ wr_re, const float* __restrict__ wr_im,
                        const float* __restrict__ wz_re, const float* __restrict__ wz_im,
                        const float* __restrict__ wh_re, const float* __restrict__ wh_im,
                        const float* __restrict__ ur_re, const float* __restrict__ ur_im,
                        const float* __restrict__ uz_re, const float* __restrict__ uz_im,
                        const float* __restrict__ uh_re, const float* __restrict__ uh_im)
{
    int idx = blockIdx.x * blockDim.x + threadIdx.x;
    int n = idx >> 10, k = idx & 1023;
    int seg = n >> 9;
    int rem = n & 511;
    int j   = rem >> 1;
    bool isIm = (rem & 1) != 0;
    int kg = k >> 8, kc = k & 255;

    const float *Wre, *Wim, *Ure, *Uim;
    if (seg == 0)      { Wre = wr_re; Wim = wr_im; Ure = ur_re; Uim = ur_im; }
    else if (seg == 1) { Wre = wz_re; Wim = wz_im; Ure = uz_re; Uim = uz_im; }
    else               { Wre = wh_re; Wim = wh_im; Ure = uh_re; Uim = uh_im; }
    bool isH = (seg == 2);

    int wj = j * 512;
    int uj = j * 256;
    float v;
    if (kg == 0) {
        v = isIm ?  Wim[wj + kc] : Wre[wj + kc];
    } else if (kg == 1) {
        v = isIm ?  Wre[wj + kc] : -Wim[wj + kc];
    } else if (kg == 2) {
        if (isIm) v = (isH ? 0.f : Wim[wj + 256 + kc]) + Uim[uj + kc];
        else      v = (isH ? 0.f : Wre[wj + 256 + kc]) + Ure[uj + kc];
    } else {
        if (isIm) v =  (isH ? 0.f : Wre[wj + 256 + kc]) + Ure[uj + kc];
        else      v = -((isH ? 0.f : Wim[wj + 256 + kc]) + Uim[uj + kc]);
    }
    g_G1h[idx] = __float2half(v);
}

// G2 column n: j = n>>1, im = n&1.
__global__ void prep_g2(const float* __restrict__ wh_re,
                        const float* __restrict__ wh_im)
{
    int idx = blockIdx.x * blockDim.x + threadIdx.x;
    int n = idx >> 9, k = idx & 511;
    int j  = n >> 1;
    bool isIm = (n & 1) != 0;
    int kg = k >> 8, kc = k & 255;
    float wre = wh_re[j * 512 + 256 + kc];
    float wim = wh_im[j * 512 + 256 + kc];
    float v = isIm ? ((kg == 0) ? wim :  wre)
                   : ((kg == 0) ? wre : -wim);
    g_G2h[idx] = __float2half(v);
}

__global__ void prep_bias(const float* __restrict__ wr_b_re, const float* __restrict__ wr_b_im,
                          const float* __restrict__ wz_b_re, const float* __restrict__ wz_b_im,
                          const float* __restrict__ wh_b_re, const float* __restrict__ wh_b_im)
{
    int idx = blockIdx.x * blockDim.x + threadIdx.x;   // < 1536
    int seg = idx >> 9;
    int rem = idx & 511;
    int j   = rem >> 1;
    bool im = (rem & 1) != 0;
    const float *br, *bi;
    if (seg == 0)      { br = wr_b_re; bi = wr_b_im; }
    else if (seg == 1) { br = wz_b_re; bi = wz_b_im; }
    else               { br = wh_b_re; bi = wh_b_im; }
    g_bias[idx] = im ? (br[j] + bi[j]) : (br[j] - bi[j]);
}

__global__ void convA(const float* __restrict__ x_re, const float* __restrict__ x_im,
                      const float* __restrict__ h_re, const float* __restrict__ h_im)
{
    int idx = blockIdx.x * blockDim.x + threadIdx.x;   // < B*256
    int b = idx >> 8;
    int k = (idx & 255) << 2;
    int plane = k >> 8, kc = k & 255;
    const float* src = (plane == 0) ? x_re : (plane == 1) ? x_im
                     : (plane == 2) ? h_re : h_im;
    float4 v = *(const float4*)(src + (size_t)b * 256 + kc);
    __half2* dst = (__half2*)(g_Ah + (size_t)b * 1024 + k);
    dst[0] = __floats2half2_rn(v.x, v.y);
    dst[1] = __floats2half2_rn(v.z, v.w);
}

// ---- fp16 tensor-core GEMM with fused epilogues ------------------------------
#define BM 128
#define BN 128
#define BKH 32
#define ROWB 80                        // bytes per smem row (64 + 16 pad)
#define A_ST (BM * ROWB)               // 10240
#define STAGE_B (2 * A_ST)             // 20480
#define STAGES 3
#define HG_SMEM (STAGES * STAGE_B)     // 61440

__global__ void __launch_bounds__(128, 2)
hgemm(int mode, const float* __restrict__ h_re, const float* __restrict__ h_im,
      float* __restrict__ out)
{
    extern __shared__ char smem[];
    const uint32_t sb = smem_u32(smem);

    const __half* A;
    const __half* W;
    int lda, N, K;
    if (mode == 0) {
        A = g_Ah;  W = g_G1h; lda = G1_K; N = G1_N; K = G1_K;
    } else {
        A = g_RHh; W = g_G2h; lda = G2_K; N = G2_N; K = G2_K;
    }

    const int tid  = threadIdx.x;
    const int lane = tid & 31;
    const int wid  = tid >> 5;
    const int wm   = wid & 1;
    const int wn   = wid >> 1;
    const int mBlk = blockIdx.y * BM;
    const int nBlk = blockIdx.x * BN;
    const int NK   = K / BKH;

    // loader: 128 threads; 4 A-rows + 4 B-rows of 16B per stage
    const int lrow = tid >> 2;
    const int seg  = tid & 3;
    const __half* gA[4];
    const __half* gB[4];
    uint32_t sA[4], sB[4];
#pragma unroll
    for (int i = 0; i < 4; ++i) {
        gA[i] = A + (size_t)(mBlk + lrow + 32 * i) * lda + seg * 8;
        gB[i] = W + (size_t)(nBlk + lrow + 32 * i) * K   + seg * 8;
        sA[i] = sb + (lrow + 32 * i) * ROWB + seg * 16;
        sB[i] = sA[i] + A_ST;
    }

    // ldmatrix lane offsets (verified fragment layout)
    const int aRow = lane & 15;
    const int aK   = (lane >> 4) << 3;
    uint32_t aOff[4];
#pragma unroll
    for (int mt = 0; mt < 4; ++mt)
        aOff[mt] = (uint32_t)((wm * 64 + mt * 16 + aRow) * ROWB + aK * 2);
    const int bRow = ((lane >> 4) << 3) + (lane & 7);
    const int bK   = lane & 8;
    uint32_t bOff[4];
#pragma unroll
    for (int p = 0; p < 4; ++p)
        bOff[p] = (uint32_t)(A_ST + (wn * 64 + p * 16 + bRow) * ROWB + bK * 2);

    float c[4][8][4];
#pragma unroll
    for (int i = 0; i < 4; ++i)
#pragma unroll
        for (int j = 0; j < 8; ++j)
#pragma unroll
            for (int r = 0; r < 4; ++r) c[i][j][r] = 0.f;

    auto load = [&](int st, int k) {
        uint32_t off = (uint32_t)(st * STAGE_B);
        int kh = k * BKH;
#pragma unroll
        for (int i = 0; i < 4; ++i) {
            cp16(sA[i] + off, gA[i] + kh);
            cp16(sB[i] + off, gB[i] + kh);
        }
    };

    load(0, 0); cp_commit();
    load(1, 1); cp_commit();

    for (int k = 0; k < NK; ++k) {
        if (k < NK - 1) cp_wait1(); else cp_wait0();
        __syncthreads();
        if (k + 2 < NK) {
            load((k + 2) % STAGES, k + 2);
            cp_commit();
        }

        const uint32_t base = (uint32_t)((k % STAGES) * STAGE_B);
#pragma unroll
        for (int kk = 0; kk < 2; ++kk) {
            const uint32_t koff = kk * 32;
            uint32_t a[4][4], b[4][4];
#pragma unroll
            for (int mt = 0; mt < 4; ++mt)
                ldsm4(a[mt], sb + base + aOff[mt] + koff);
#pragma unroll
            for (int p = 0; p < 4; ++p)
                ldsm4(b[p], sb + base + bOff[p] + koff);
#pragma unroll
            for (int mt = 0; mt < 4; ++mt)
#pragma unroll
                for (int nt = 0; nt < 8; ++nt)
                    mma_f16(c[mt][nt], a[mt], &b[nt >> 1][(nt & 1) * 2]);
        }
    }

    // ---- fused epilogues ----
    const int grp = lane >> 2;
    const int qid = lane & 3;

    if (mode == 0 && nBlk < 512) {
        // r segment: sigmoid + complex r(*)h -> g_RHh
#pragma unroll
        for (int mt = 0; mt < 4; ++mt) {
#pragma unroll
            for (int nt = 0; nt < 8; ++nt) {
                int col = nBlk + wn * 64 + nt * 8 + qid * 2;  // even
                int j   = col >> 1;
                float bre = g_bias[col], bim = g_bias[col + 1];
#pragma unroll
                for (int rr_ = 0; rr_ < 2; ++rr_) {
                    int row = mBlk + wm * 64 + mt * 16 + grp + rr_ * 8;
                    float cre = c[mt][nt][rr_ * 2 + 0];
                    float cim = c[mt][nt][rr_ * 2 + 1];
                    float rr = sigmoidf_(cre + bre);
                    float ri = sigmoidf_(cim + bim);
                    float hr = h_re[(size_t)row * 256 + j];
                    float hi = h_im[(size_t)row * 256 + j];
                    g_RHh[(size_t)row * 512 + j] =
                        __float2half(rr * hr - ri * hi);
                    g_RHh[(size_t)row * 512 + 256 + j] =
                        __float2half(rr * hi + ri * hr);
                }
            }
        }
    } else if (mode == 0) {
        // z / ph segments: store fp16 C1
#pragma unroll
        for (int mt = 0; mt < 4; ++mt) {
#pragma unroll
            for (int nt = 0; nt < 8; ++nt) {
                int row = mBlk + wm * 64 + mt * 16 + grp;
                int col = nBlk + wn * 64 + nt * 8 + qid * 2;
                *(__half2*)&g_C1h[(size_t)row * G1_N + col] =
                    __floats2half2_rn(c[mt][nt][0], c[mt][nt][1]);
                *(__half2*)&g_C1h[(size_t)(row + 8) * G1_N + col] =
                    __floats2half2_rn(c[mt][nt][2], c[mt][nt][3]);
            }
        }
    } else {
        // GEMM2: fused e2 -> out
#pragma unroll
        for (int mt = 0; mt < 4; ++mt) {
#pragma unroll
            for (int nt = 0; nt < 8; ++nt) {
                int col = nBlk + wn * 64 + nt * 8 + qid * 2;  // even, col = 2j
                int j   = col >> 1;
                float bzr = g_bias[512 + col],  bzi = g_bias[512 + col + 1];
                float bpr = g_bias[1024 + col], bpi = g_bias[1024 + col + 1];
#pragma unroll
                for (int rr_ = 0; rr_ < 2; ++rr_) {
                    int row = mBlk + wm * 64 + mt * 16 + grp + rr_ * 8;
                    size_t r1 = (size_t)row * G1_N;
                    __half2 zh = *(const __half2*)&g_C1h[r1 + 512 + col];
                    __half2 ph = *(const __half2*)&g_C1h[r1 + 1024 + col];
                    float zr = sigmoidf_(__low2float(zh)  + bzr);
                    float zi = sigmoidf_(__high2float(zh) + bzi);
                    float er = c[mt][nt][rr_ * 2 + 0] + __low2float(ph)  + bpr;
                    float ei = c[mt][nt][rr_ * 2 + 1] + __high2float(ph) + bpi;
                    float hhr = tanhf(er);
                    float hhi = tanhf(ei);
                    float hr = h_re[(size_t)row * 256 + j];
                    float hi = h_im[(size_t)row * 256 + j];
                    out[(size_t)row * 256 + j] =
                        (1.0f - zr) * hr + zi * hi + zr * hhr - zi * hhi;
                    out[(size_t)B_ROWS * HDIM + (size_t)row * 256 + j] =
                        (1.0f - zr) * hi - zi * hr + zr * hhi + zi * hhr;
                }
            }
        }
    }
}

// ---- launch -------------------------------------------------------------------
extern "C" void kernel_launch(void* const* d_in, const int* in_sizes, int n_in,
                              void* d_out, int out_size)
{
    const float* x_re    = (const float*)d_in[0];
    const float* x_im    = (const float*)d_in[1];
    const float* h_re    = (const float*)d_in[2];
    const float* h_im    = (const float*)d_in[3];
    const float* wr_w_re = (const float*)d_in[4];
    const float* wr_w_im = (const float*)d_in[5];
    const float* wr_b_re = (const float*)d_in[6];
    const float* wr_b_im = (const float*)d_in[7];
    const float* wz_w_re = (const float*)d_in[8];
    const float* wz_w_im = (const float*)d_in[9];
    const float* wz_b_re = (const float*)d_in[10];
    const float* wz_b_im = (const float*)d_in[11];
    const float* wh_w_re = (const float*)d_in[12];
    const float* wh_w_im = (const float*)d_in[13];
    const float* wh_b_re = (const float*)d_in[14];
    const float* wh_b_im = (const float*)d_in[15];
    const float* ur_w_re = (const float*)d_in[16];
    const float* ur_w_im = (const float*)d_in[17];
    const float* uz_w_re = (const float*)d_in[18];
    const float* uz_w_im = (const float*)d_in[19];
    const float* uh_w_re = (const float*)d_in[20];
    const float* uh_w_im = (const float*)d_in[21];
    float* out = (float*)d_out;

    static int smem_set = 0;
    if (!smem_set) {
        cudaFuncSetAttribute(hgemm, cudaFuncAttributeMaxDynamicSharedMemorySize,
                             HG_SMEM);
        smem_set = 1;
    }

    prep_g1<<<(G1_N * G1_K) / 256, 256>>>(wr_w_re, wr_w_im, wz_w_re, wz_w_im,
                                          wh_w_re, wh_w_im, ur_w_re, ur_w_im,
                                          uz_w_re, uz_w_im, uh_w_re, uh_w_im);
    prep_g2<<<(G2_N * G2_K) / 256, 256>>>(wh_w_re, wh_w_im);
    prep_bias<<<G1_N / 256, 256>>>(wr_b_re, wr_b_im, wz_b_re, wz_b_im,
                                   wh_b_re, wh_b_im);
    convA<<<(B_ROWS * 256) / 256, 256>>>(x_re, x_im, h_re, h_im);

    dim3 blk(128);
    dim3 grid1(G1_N / BN, B_ROWS / BM);   // 12 x 128
    hgemm<<<grid1, blk, HG_SMEM>>>(0, h_re, h_im, out);

    dim3 grid2(G2_N / BN, B_ROWS / BM);   // 4 x 128
    hgemm<<<grid2, blk, HG_SMEM>>>(1, h_re, h_im, out);
}

// round 11
// speedup vs baseline: 1.2588x; 1.2588x over previous
#include <cuda_runtime.h>
#include <cuda_fp16.h>
#include <cstdint>

// ---------------------------------------------------------------------------
// complexGRUCell: B=16384, I=256, H=256, fp32 in/out.
// fp16 tensor-core GEMMs (mma.m16n8k16) with ldmatrix + 3-stage cp.async.
// CTA 128x128, 128 threads = 4 warps (2m x 2n), warp tile 64x64, 2 CTA/SM.
// BK = 64 halves per stage (16 mainloop iterations for K=1024).
// C1/C2 intermediates stored fp16. Separate coalesced e1/e2 kernels.
// __device__ globals resolved INSIDE device code (GB300/ATS host-shadow trap).
// ---------------------------------------------------------------------------

#define B_ROWS 16384
#define HDIM   256
#define G1_N   1536
#define G1_K   1024
#define G2_N   512
#define G2_K   512

__device__ __half g_G1h[G1_N * G1_K];
__device__ __half g_G2h[G2_N * G2_K];
__device__ __half g_Ah[(size_t)B_ROWS * G1_K];
__device__ __half g_RHh[(size_t)B_ROWS * 512];
__device__ float  g_bias[G1_N];
__device__ __half g_C1h[(size_t)B_ROWS * G1_N];
__device__ __half g_C2h[(size_t)B_ROWS * 512];

// ---- PTX helpers ------------------------------------------------------------
__device__ __forceinline__ uint32_t smem_u32(const void* p) {
    uint32_t a;
    asm("{ .reg .u64 t; cvta.to.shared.u64 t, %1; cvt.u32.u64 %0, t; }"
        : "=r"(a) : "l"(p));
    return a;
}
__device__ __forceinline__ void cp16(uint32_t s, const void* g) {
    asm volatile("cp.async.cg.shared.global [%0], [%1], 16;" :: "r"(s), "l"(g));
}
__device__ __forceinline__ void cp_commit() {
    asm volatile("cp.async.commit_group;" ::: "memory");
}
__device__ __forceinline__ void cp_wait1() {
    asm volatile("cp.async.wait_group 1;" ::: "memory");
}
__device__ __forceinline__ void cp_wait0() {
    asm volatile("cp.async.wait_group 0;" ::: "memory");
}
__device__ __forceinline__ void ldsm4(uint32_t* r, uint32_t addr) {
    asm volatile("ldmatrix.sync.aligned.m8n8.x4.shared.b16 {%0,%1,%2,%3}, [%4];"
                 : "=r"(r[0]), "=r"(r[1]), "=r"(r[2]), "=r"(r[3]) : "r"(addr));
}
__device__ __forceinline__ void mma_f16(float* c, const uint32_t* a,
                                        const uint32_t* b) {
    asm volatile(
        "mma.sync.aligned.m16n8k16.row.col.f32.f16.f16.f32 "
        "{%0,%1,%2,%3}, {%4,%5,%6,%7}, {%8,%9}, {%0,%1,%2,%3};"
        : "+f"(c[0]), "+f"(c[1]), "+f"(c[2]), "+f"(c[3])
        : "r"(a[0]), "r"(a[1]), "r"(a[2]), "r"(a[3]), "r"(b[0]), "r"(b[1]));
}

// ---- weight / activation preparation ----------------------------------------
__global__ void prep_g1(const float* __restrict__ wr_re, const float* __restrict__ wr_im,
                        const float* __restrict__ wz_re, const float* __restrict__ wz_im,
                        const float* __restrict__ wh_re, const float* __restrict__ wh_im,
                        const float* __restrict__ ur_re, const float* __restrict__ ur_im,
                        const float* __restrict__ uz_re, const float* __restrict__ uz_im,
                        const float* __restrict__ uh_re, const float* __restrict__ uh_im)
{
    int idx = blockIdx.x * blockDim.x + threadIdx.x;
    int n = idx >> 10, k = idx & 1023;
    int g = n >> 8,  j = n & 255;
    int kg = k >> 8, kc = k & 255;

    const float *Wre, *Wim, *Ure, *Uim;
    if (g < 2)      { Wre = wr_re; Wim = wr_im; Ure = ur_re; Uim = ur_im; }
    else if (g < 4) { Wre = wz_re; Wim = wz_im; Ure = uz_re; Uim = uz_im; }
    else            { Wre = wh_re; Wim = wh_im; Ure = uh_re; Uim = uh_im; }
    bool isIm = (g & 1) != 0;
    bool isH  = (g >= 4);

    int wj = j * 512;
    int uj = j * 256;
    float v;
    if (kg == 0) {
        v = isIm ?  Wim[wj + kc] : Wre[wj + kc];
    } else if (kg == 1) {
        v = isIm ?  Wre[wj + kc] : -Wim[wj + kc];
    } else if (kg == 2) {
        if (isIm) v = (isH ? 0.f : Wim[wj + 256 + kc]) + Uim[uj + kc];
        else      v = (isH ? 0.f : Wre[wj + 256 + kc]) + Ure[uj + kc];
    } else {
        if (isIm) v =  (isH ? 0.f : Wre[wj + 256 + kc]) + Ure[uj + kc];
        else      v = -((isH ? 0.f : Wim[wj + 256 + kc]) + Uim[uj + kc]);
    }
    g_G1h[idx] = __float2half(v);
}

__global__ void prep_g2(const float* __restrict__ wh_re,
                        const float* __restrict__ wh_im)
{
    int idx = blockIdx.x * blockDim.x + threadIdx.x;
    int n = idx >> 9, k = idx & 511;
    int g = n >> 8,  j = n & 255;
    int kg = k >> 8, kc = k & 255;
    float wre = wh_re[j * 512 + 256 + kc];
    float wim = wh_im[j * 512 + 256 + kc];
    float v = (g == 0) ? ((kg == 0) ? wre : -wim)
                       : ((kg == 0) ? wim :  wre);
    g_G2h[idx] = __float2half(v);
}

__global__ void prep_bias(const float* __restrict__ wr_b_re, const float* __restrict__ wr_b_im,
                          const float* __restrict__ wz_b_re, const float* __restrict__ wz_b_im,
                          const float* __restrict__ wh_b_re, const float* __restrict__ wh_b_im)
{
    int idx = blockIdx.x * blockDim.x + threadIdx.x;
    int g = idx >> 8, j = idx & 255;
    const float *br, *bi;
    if (g < 2)      { br = wr_b_re; bi = wr_b_im; }
    else if (g < 4) { br = wz_b_re; bi = wz_b_im; }
    else            { br = wh_b_re; bi = wh_b_im; }
    g_bias[idx] = (g & 1) ? (br[j] + bi[j]) : (br[j] - bi[j]);
}

__global__ void convA(const float* __restrict__ x_re, const float* __restrict__ x_im,
                      const float* __restrict__ h_re, const float* __restrict__ h_im)
{
    int idx = blockIdx.x * blockDim.x + threadIdx.x;   // < B*256
    int b = idx >> 8;
    int k = (idx & 255) << 2;
    int plane = k >> 8, kc = k & 255;
    const float* src = (plane == 0) ? x_re : (plane == 1) ? x_im
                     : (plane == 2) ? h_re : h_im;
    float4 v = *(const float4*)(src + (size_t)b * 256 + kc);
    __half2* dst = (__half2*)(g_Ah + (size_t)b * 1024 + k);
    dst[0] = __floats2half2_rn(v.x, v.y);
    dst[1] = __floats2half2_rn(v.z, v.w);
}

// ---- fp16 tensor-core GEMM: C[M,N] = A[M,K] @ W[N,K]^T, C in fp16 ----------
// CTA 128x128, BK=64 halves, 3 cp.async stages, 4 warps (2m x 2n),
// warp tile 64x64, m16n8k16, ldmatrix.x4.
#define BM 128
#define BN 128
#define BKH 64
#define ROWB 144                       // bytes per smem row (128 + 16 pad)
#define A_ST (BM * ROWB)               // 18432
#define STAGE_B (2 * A_ST)             // 36864
#define STAGES 3
#define HG_SMEM (STAGES * STAGE_B)     // 110592

__global__ void __launch_bounds__(128, 2)
hgemm(int mode)
{
    extern __shared__ char smem[];
    const uint32_t sb = smem_u32(smem);

    const __half* A;
    const __half* W;
    __half* C;
    int lda, N, K;
    if (mode == 0) {
        A = g_Ah;  W = g_G1h; C = g_C1h; lda = G1_K; N = G1_N; K = G1_K;
    } else {
        A = g_RHh; W = g_G2h; C = g_C2h; lda = G2_K; N = G2_N; K = G2_K;
    }

    const int tid  = threadIdx.x;
    const int lane = tid & 31;
    const int wid  = tid >> 5;
    const int wm   = wid & 1;          // m-warp (0..1)
    const int wn   = wid >> 1;         // n-warp (0..1), 64 cols each
    const int mBlk = blockIdx.y * BM;
    const int nBlk = blockIdx.x * BN;
    const int NK   = K / BKH;

    // loader: 128 threads; 16 rows x 8 segments per pass, 8 passes each for A,B
    const int lrow8 = tid >> 3;        // 0..15
    const int seg8  = tid & 7;         // 0..7 (16B each, 128B row)
    const __half* gA0 = A + (size_t)(mBlk + lrow8) * lda + seg8 * 8;
    const __half* gB0 = W + (size_t)(nBlk + lrow8) * K   + seg8 * 8;
    const uint32_t sA0 = sb + lrow8 * ROWB + seg8 * 16;
    const uint32_t sB0 = sA0 + A_ST;
    const int strideA = 16 * lda;      // halves per 16 rows
    const int strideB = 16 * K;

    // ldmatrix lane offsets (verified fragment layout)
    const int aRow = lane & 15;
    const int aK   = (lane >> 4) << 3;
    uint32_t aOff[4];
#pragma unroll
    for (int mt = 0; mt < 4; ++mt)
        aOff[mt] = (uint32_t)((wm * 64 + mt * 16 + aRow) * ROWB + aK * 2);
    const int bRow = ((lane >> 4) << 3) + (lane & 7);
    const int bK   = lane & 8;
    uint32_t bOff[4];
#pragma unroll
    for (int p = 0; p < 4; ++p)
        bOff[p] = (uint32_t)(A_ST + (wn * 64 + p * 16 + bRow) * ROWB + bK * 2);

    float c[4][8][4];
#pragma unroll
    for (int i = 0; i < 4; ++i)
#pragma unroll
        for (int j = 0; j < 8; ++j)
#pragma unroll
            for (int r = 0; r < 4; ++r) c[i][j][r] = 0.f;

    auto load = [&](int st, int k) {
        uint32_t off = (uint32_t)(st * STAGE_B);
        int kh = k * BKH;
#pragma unroll
        for (int i = 0; i < 8; ++i) {
            cp16(sA0 + off + i * 16 * ROWB, gA0 + kh + i * strideA);
            cp16(sB0 + off + i * 16 * ROWB, gB0 + kh + i * strideB);
        }
    };

    load(0, 0); cp_commit();
    load(1, 1); cp_commit();

    for (int k = 0; k < NK; ++k) {
        if (k < NK - 1) cp_wait1(); else cp_wait0();
        __syncthreads();
        if (k + 2 < NK) {
            load((k + 2) % STAGES, k + 2);
            cp_commit();
        }

        const uint32_t base = (uint32_t)((k % STAGES) * STAGE_B);
#pragma unroll
        for (int kk = 0; kk < 4; ++kk) {
            const uint32_t koff = kk * 32;   // 16 halves = 32 bytes
            uint32_t a[4][4], b[4][4];
#pragma unroll
            for (int mt = 0; mt < 4; ++mt)
                ldsm4(a[mt], sb + base + aOff[mt] + koff);
#pragma unroll
            for (int p = 0; p < 4; ++p)
                ldsm4(b[p], sb + base + bOff[p] + koff);
#pragma unroll
            for (int mt = 0; mt < 4; ++mt)
#pragma unroll
                for (int nt = 0; nt < 8; ++nt)
                    mma_f16(c[mt][nt], a[mt], &b[nt >> 1][(nt & 1) * 2]);
        }
    }

    // epilogue: fp32 acc -> fp16 C
    const int grp = lane >> 2;
    const int qid = lane & 3;
#pragma unroll
    for (int mt = 0; mt < 4; ++mt) {
#pragma unroll
        for (int nt = 0; nt < 8; ++nt) {
            int row = mBlk + wm * 64 + mt * 16 + grp;
            int col = nBlk + wn * 64 + nt * 8 + qid * 2;
            *(__half2*)&C[(size_t)row * N + col] =
                __floats2half2_rn(c[mt][nt][0], c[mt][nt][1]);
            *(__half2*)&C[(size_t)(row + 8) * N + col] =
                __floats2half2_rn(c[mt][nt][2], c[mt][nt][3]);
        }
    }
}

// ---- elementwise -------------------------------------------------------------
__device__ __forceinline__ float sigmoidf_(float x) {
    return 1.0f / (1.0f + __expf(-x));
}

__global__ void e1_kernel(const float* __restrict__ h_re,
                          const float* __restrict__ h_im)
{
    int idx = blockIdx.x * blockDim.x + threadIdx.x;
    int b = idx >> 8, j = idx & 255;
    size_t row = (size_t)b * G1_N;
    float rr = sigmoidf_(__half2float(g_C1h[row + j])       + g_bias[j]);
    float ri = sigmoidf_(__half2float(g_C1h[row + 256 + j]) + g_bias[256 + j]);
    float hr = h_re[idx], hi = h_im[idx];
    size_t r2 = (size_t)b * 512;
    g_RHh[r2 + j]       = __float2half(rr * hr - ri * hi);
    g_RHh[r2 + 256 + j] = __float2half(rr * hi + ri * hr);
}

__global__ void e2_kernel(const float* __restrict__ h_re,
                          const float* __restrict__ h_im,
                          float* __restrict__ out)
{
    int idx = blockIdx.x * blockDim.x + threadIdx.x;
    int b = idx >> 8, j = idx & 255;
    size_t r1 = (size_t)b * G1_N;
    size_t r2 = (size_t)b * 512;
    float zr = sigmoidf_(__half2float(g_C1h[r1 + 512 + j]) + g_bias[512 + j]);
    float zi = sigmoidf_(__half2float(g_C1h[r1 + 768 + j]) + g_bias[768 + j]);
    float er = __half2float(g_C2h[r2 + j])
             + __half2float(g_C1h[r1 + 1024 + j]) + g_bias[1024 + j];
    float ei = __half2float(g_C2h[r2 + 256 + j])
             + __half2float(g_C1h[r1 + 1280 + j]) + g_bias[1280 + j];
    float hhr = tanhf(er);
    float hhi = tanhf(ei);
    float hr = h_re[idx], hi = h_im[idx];
    out[idx] = (1.0f - zr) * hr + zi * hi + zr * hhr - zi * hhi;
    out[(size_t)B_ROWS * HDIM + idx] =
        (1.0f - zr) * hi - zi * hr + zr * hhi + zi * hhr;
}

// ---- launch -------------------------------------------------------------------
extern "C" void kernel_launch(void* const* d_in, const int* in_sizes, int n_in,
                              void* d_out, int out_size)
{
    const float* x_re    = (const float*)d_in[0];
    const float* x_im    = (const float*)d_in[1];
    const float* h_re    = (const float*)d_in[2];
    const float* h_im    = (const float*)d_in[3];
    const float* wr_w_re = (const float*)d_in[4];
    const float* wr_w_im = (const float*)d_in[5];
    const float* wr_b_re = (const float*)d_in[6];
    const float* wr_b_im = (const float*)d_in[7];
    const float* wz_w_re = (const float*)d_in[8];
    const float* wz_w_im = (const float*)d_in[9];
    const float* wz_b_re = (const float*)d_in[10];
    const float* wz_b_im = (const float*)d_in[11];
    const float* wh_w_re = (const float*)d_in[12];
    const float* wh_w_im = (const float*)d_in[13];
    const float* wh_b_re = (const float*)d_in[14];
    const float* wh_b_im = (const float*)d_in[15];
    const float* ur_w_re = (const float*)d_in[16];
    const float* ur_w_im = (const float*)d_in[17];
    const float* uz_w_re = (const float*)d_in[18];
    const float* uz_w_im = (const float*)d_in[19];
    const float* uh_w_re = (const float*)d_in[20];
    const float* uh_w_im = (const float*)d_in[21];

    static int smem_set = 0;
    if (!smem_set) {
        cudaFuncSetAttribute(hgemm, cudaFuncAttributeMaxDynamicSharedMemorySize,
                             HG_SMEM);
        smem_set = 1;
    }

    prep_g1<<<(G1_N * G1_K) / 256, 256>>>(wr_w_re, wr_w_im, wz_w_re, wz_w_im,
                                          wh_w_re, wh_w_im, ur_w_re, ur_w_im,
                                          uz_w_re, uz_w_im, uh_w_re, uh_w_im);
    prep_g2<<<(G2_N * G2_K) / 256, 256>>>(wh_w_re, wh_w_im);
    prep_bias<<<G1_N / 256, 256>>>(wr_b_re, wr_b_im, wz_b_re, wz_b_im,
                                   wh_b_re, wh_b_im);
    convA<<<(B_ROWS * 256) / 256, 256>>>(x_re, x_im, h_re, h_im);

    dim3 blk(128);
    dim3 grid1(G1_N / BN, B_ROWS / BM);   // 12 x 128
    hgemm<<<grid1, blk, HG_SMEM>>>(0);

    e1_kernel<<<(B_ROWS * HDIM) / 256, 256>>>(h_re, h_im);

    dim3 grid2(G2_N / BN, B_ROWS / BM);   // 4 x 128
    hgemm<<<grid2, blk, HG_SMEM>>>(1);

    e2_kernel<<<(B_ROWS * HDIM) / 256, 256>>>(h_re, h_im, (float*)d_out);
}

// round 12
// speedup vs baseline: 1.3556x; 1.0769x over previous
#include <cuda_runtime.h>
#include <cuda_fp16.h>
#include <cstdint>

// ---------------------------------------------------------------------------
// complexGRUCell: B=16384, I=256, H=256, fp32 in/out.
// fp16 tensor-core GEMMs (mma.m16n8k16) with ldmatrix + 3-stage cp.async.
// CTA 128x128, 128 threads = 4 warps (2m x 2n), warp tile 64x64, 2 CTA/SM.
// BK=32; fragments for BOTH kk-groups loaded up-front each chunk (software
// pipelining of LDSM under MMA). C1/C2 intermediates fp16.
// __device__ globals resolved INSIDE device code (GB300/ATS host-shadow trap).
// ---------------------------------------------------------------------------

#define B_ROWS 16384
#define HDIM   256
#define G1_N   1536
#define G1_K   1024
#define G2_N   512
#define G2_K   512

__device__ __half g_G1h[G1_N * G1_K];
__device__ __half g_G2h[G2_N * G2_K];
__device__ __half g_Ah[(size_t)B_ROWS * G1_K];
__device__ __half g_RHh[(size_t)B_ROWS * 512];
__device__ float  g_bias[G1_N];
__device__ __half g_C1h[(size_t)B_ROWS * G1_N];
__device__ __half g_C2h[(size_t)B_ROWS * 512];

// ---- PTX helpers ------------------------------------------------------------
__device__ __forceinline__ uint32_t smem_u32(const void* p) {
    uint32_t a;
    asm("{ .reg .u64 t; cvta.to.shared.u64 t, %1; cvt.u32.u64 %0, t; }"
        : "=r"(a) : "l"(p));
    return a;
}
__device__ __forceinline__ void cp16(uint32_t s, const void* g) {
    asm volatile("cp.async.cg.shared.global [%0], [%1], 16;" :: "r"(s), "l"(g));
}
__device__ __forceinline__ void cp_commit() {
    asm volatile("cp.async.commit_group;" ::: "memory");
}
__device__ __forceinline__ void cp_wait1() {
    asm volatile("cp.async.wait_group 1;" ::: "memory");
}
__device__ __forceinline__ void cp_wait0() {
    asm volatile("cp.async.wait_group 0;" ::: "memory");
}
__device__ __forceinline__ void ldsm4(uint32_t* r, uint32_t addr) {
    asm volatile("ldmatrix.sync.aligned.m8n8.x4.shared.b16 {%0,%1,%2,%3}, [%4];"
                 : "=r"(r[0]), "=r"(r[1]), "=r"(r[2]), "=r"(r[3]) : "r"(addr));
}
__device__ __forceinline__ void mma_f16(float* c, const uint32_t* a,
                                        const uint32_t* b) {
    asm volatile(
        "mma.sync.aligned.m16n8k16.row.col.f32.f16.f16.f32 "
        "{%0,%1,%2,%3}, {%4,%5,%6,%7}, {%8,%9}, {%0,%1,%2,%3};"
        : "+f"(c[0]), "+f"(c[1]), "+f"(c[2]), "+f"(c[3])
        : "r"(a[0]), "r"(a[1]), "r"(a[2]), "r"(a[3]), "r"(b[0]), "r"(b[1]));
}

// ---- weight / activation preparation ----------------------------------------
__global__ void prep_g1(const float* __restrict__ wr_re, const float* __restrict__ wr_im,
                        const float* __restrict__ wz_re, const float* __restrict__ wz_im,
                        const float* __restrict__ wh_re, const float* __restrict__ wh_im,
                        const float* __restrict__ ur_re, const float* __restrict__ ur_im,
                        const float* __restrict__ uz_re, const float* __restrict__ uz_im,
                        const float* __restrict__ uh_re, const float* __restrict__ uh_im)
{
    int idx = blockIdx.x * blockDim.x + threadIdx.x;
    int n = idx >> 10, k = idx & 1023;
    int g = n >> 8,  j = n & 255;
    int kg = k >> 8, kc = k & 255;

    const float *Wre, *Wim, *Ure, *Uim;
    if (g < 2)      { Wre = wr_re; Wim = wr_im; Ure = ur_re; Uim = ur_im; }
    else if (g < 4) { Wre = wz_re; Wim = wz_im; Ure = uz_re; Uim = uz_im; }
    else            { Wre = wh_re; Wim = wh_im; Ure = uh_re; Uim = uh_im; }
    bool isIm = (g & 1) != 0;
    bool isH  = (g >= 4);

    int wj = j * 512;
    int uj = j * 256;
    float v;
    if (kg == 0) {
        v = isIm ?  Wim[wj + kc] : Wre[wj + kc];
    } else if (kg == 1) {
        v = isIm ?  Wre[wj + kc] : -Wim[wj + kc];
    } else if (kg == 2) {
        if (isIm) v = (isH ? 0.f : Wim[wj + 256 + kc]) + Uim[uj + kc];
        else      v = (isH ? 0.f : Wre[wj + 256 + kc]) + Ure[uj + kc];
    } else {
        if (isIm) v =  (isH ? 0.f : Wre[wj + 256 + kc]) + Ure[uj + kc];
        else      v = -((isH ? 0.f : Wim[wj + 256 + kc]) + Uim[uj + kc]);
    }
    g_G1h[idx] = __float2half(v);
}

__global__ void prep_g2(const float* __restrict__ wh_re,
                        const float* __restrict__ wh_im)
{
    int idx = blockIdx.x * blockDim.x + threadIdx.x;
    int n = idx >> 9, k = idx & 511;
    int g = n >> 8,  j = n & 255;
    int kg = k >> 8, kc = k & 255;
    float wre = wh_re[j * 512 + 256 + kc];
    float wim = wh_im[j * 512 + 256 + kc];
    float v = (g == 0) ? ((kg == 0) ? wre : -wim)
                       : ((kg == 0) ? wim :  wre);
    g_G2h[idx] = __float2half(v);
}

__global__ void prep_bias(const float* __restrict__ wr_b_re, const float* __restrict__ wr_b_im,
                          const float* __restrict__ wz_b_re, const float* __restrict__ wz_b_im,
                          const float* __restrict__ wh_b_re, const float* __restrict__ wh_b_im)
{
    int idx = blockIdx.x * blockDim.x + threadIdx.x;
    int g = idx >> 8, j = idx & 255;
    const float *br, *bi;
    if (g < 2)      { br = wr_b_re; bi = wr_b_im; }
    else if (g < 4) { br = wz_b_re; bi = wz_b_im; }
    else            { br = wh_b_re; bi = wh_b_im; }
    g_bias[idx] = (g & 1) ? (br[j] + bi[j]) : (br[j] - bi[j]);
}

__global__ void convA(const float* __restrict__ x_re, const float* __restrict__ x_im,
                      const float* __restrict__ h_re, const float* __restrict__ h_im)
{
    int idx = blockIdx.x * blockDim.x + threadIdx.x;   // < B*256
    int b = idx >> 8;
    int k = (idx & 255) << 2;
    int plane = k >> 8, kc = k & 255;
    const float* src = (plane == 0) ? x_re : (plane == 1) ? x_im
                     : (plane == 2) ? h_re : h_im;
    float4 v = *(const float4*)(src + (size_t)b * 256 + kc);
    __half2* dst = (__half2*)(g_Ah + (size_t)b * 1024 + k);
    dst[0] = __floats2half2_rn(v.x, v.y);
    dst[1] = __floats2half2_rn(v.z, v.w);
}

// ---- fp16 tensor-core GEMM: C[M,N] = A[M,K] @ W[N,K]^T, C in fp16 ----------
// CTA 128x128, BK=32 halves, 3 cp.async stages, 4 warps (2m x 2n),
// warp tile 64x64, m16n8k16, ldmatrix.x4, fragment SW pipeline.
#define BM 128
#define BN 128
#define BKH 32
#define ROWB 80                        // bytes per smem row (64 + 16 pad)
#define A_ST (BM * ROWB)               // 10240
#define STAGE_B (2 * A_ST)             // 20480
#define STAGES 3
#define HG_SMEM (STAGES * STAGE_B)     // 61440

__global__ void __launch_bounds__(128, 2)
hgemm(int mode)
{
    extern __shared__ char smem[];
    const uint32_t sb = smem_u32(smem);

    const __half* A;
    const __half* W;
    __half* C;
    int lda, N, K;
    if (mode == 0) {
        A = g_Ah;  W = g_G1h; C = g_C1h; lda = G1_K; N = G1_N; K = G1_K;
    } else {
        A = g_RHh; W = g_G2h; C = g_C2h; lda = G2_K; N = G2_N; K = G2_K;
    }

    const int tid  = threadIdx.x;
    const int lane = tid & 31;
    const int wid  = tid >> 5;
    const int wm   = wid & 1;
    const int wn   = wid >> 1;
    const int mBlk = blockIdx.y * BM;
    const int nBlk = blockIdx.x * BN;
    const int NK   = K / BKH;

    // loader: 128 threads; 4 A-rows + 4 B-rows of 16B per stage
    const int lrow = tid >> 2;
    const int seg  = tid & 3;
    const __half* gA[4];
    const __half* gB[4];
    uint32_t sA[4], sB[4];
#pragma unroll
    for (int i = 0; i < 4; ++i) {
        gA[i] = A + (size_t)(mBlk + lrow + 32 * i) * lda + seg * 8;
        gB[i] = W + (size_t)(nBlk + lrow + 32 * i) * K   + seg * 8;
        sA[i] = sb + (lrow + 32 * i) * ROWB + seg * 16;
        sB[i] = sA[i] + A_ST;
    }

    // ldmatrix lane offsets (verified fragment layout)
    const int aRow = lane & 15;
    const int aK   = (lane >> 4) << 3;
    uint32_t aOff[4];
#pragma unroll
    for (int mt = 0; mt < 4; ++mt)
        aOff[mt] = (uint32_t)((wm * 64 + mt * 16 + aRow) * ROWB + aK * 2);
    const int bRow = ((lane >> 4) << 3) + (lane & 7);
    const int bK   = lane & 8;
    uint32_t bOff[4];
#pragma unroll
    for (int p = 0; p < 4; ++p)
        bOff[p] = (uint32_t)(A_ST + (wn * 64 + p * 16 + bRow) * ROWB + bK * 2);

    float c[4][8][4];
#pragma unroll
    for (int i = 0; i < 4; ++i)
#pragma unroll
        for (int j = 0; j < 8; ++j)
#pragma unroll
            for (int r = 0; r < 4; ++r) c[i][j][r] = 0.f;

    auto load = [&](int st, int k) {
        uint32_t off = (uint32_t)(st * STAGE_B);
        int kh = k * BKH;
#pragma unroll
        for (int i = 0; i < 4; ++i) {
            cp16(sA[i] + off, gA[i] + kh);
            cp16(sB[i] + off, gB[i] + kh);
        }
    };

    load(0, 0); cp_commit();
    load(1, 1); cp_commit();

    for (int k = 0; k < NK; ++k) {
        if (k < NK - 1) cp_wait1(); else cp_wait0();
        __syncthreads();

        const uint32_t base = (uint32_t)((k % STAGES) * STAGE_B);

        // load ALL fragments for both kk-groups first ...
        uint32_t a[2][4][4], b[2][4][4];
#pragma unroll
        for (int mt = 0; mt < 4; ++mt)
            ldsm4(a[0][mt], sb + base + aOff[mt]);
#pragma unroll
        for (int p = 0; p < 4; ++p)
            ldsm4(b[0][p], sb + base + bOff[p]);
#pragma unroll
        for (int mt = 0; mt < 4; ++mt)
            ldsm4(a[1][mt], sb + base + aOff[mt] + 32);
#pragma unroll
        for (int p = 0; p < 4; ++p)
            ldsm4(b[1][p], sb + base + bOff[p] + 32);

        // ... issue next-chunk cp.async inside the ldsm latency shadow ...
        if (k + 2 < NK) {
            load((k + 2) % STAGES, k + 2);
            cp_commit();
        }

        // ... then all 64 MMAs
#pragma unroll
        for (int kk = 0; kk < 2; ++kk)
#pragma unroll
            for (int mt = 0; mt < 4; ++mt)
#pragma unroll
                for (int nt = 0; nt < 8; ++nt)
                    mma_f16(c[mt][nt], a[kk][mt], &b[kk][nt >> 1][(nt & 1) * 2]);
    }

    // epilogue: fp32 acc -> fp16 C
    const int grp = lane >> 2;
    const int qid = lane & 3;
#pragma unroll
    for (int mt = 0; mt < 4; ++mt) {
#pragma unroll
        for (int nt = 0; nt < 8; ++nt) {
            int row = mBlk + wm * 64 + mt * 16 + grp;
            int col = nBlk + wn * 64 + nt * 8 + qid * 2;
            *(__half2*)&C[(size_t)row * N + col] =
                __floats2half2_rn(c[mt][nt][0], c[mt][nt][1]);
            *(__half2*)&C[(size_t)(row + 8) * N + col] =
                __floats2half2_rn(c[mt][nt][2], c[mt][nt][3]);
        }
    }
}

// ---- elementwise -------------------------------------------------------------
__device__ __forceinline__ float sigmoidf_(float x) {
    return 1.0f / (1.0f + __expf(-x));
}

__global__ void e1_kernel(const float* __restrict__ h_re,
                          const float* __restrict__ h_im)
{
    int idx = blockIdx.x * blockDim.x + threadIdx.x;
    int b = idx >> 8, j = idx & 255;
    size_t row = (size_t)b * G1_N;
    float rr = sigmoidf_(__half2float(g_C1h[row + j])       + g_bias[j]);
    float ri = sigmoidf_(__half2float(g_C1h[row + 256 + j]) + g_bias[256 + j]);
    float hr = h_re[idx], hi = h_im[idx];
    size_t r2 = (size_t)b * 512;
    g_RHh[r2 + j]       = __float2half(rr * hr - ri * hi);
    g_RHh[r2 + 256 + j] = __float2half(rr * hi + ri * hr);
}

__global__ void e2_kernel(const float* __restrict__ h_re,
                          const float* __restrict__ h_im,
                          float* __restrict__ out)
{
    int idx = blockIdx.x * blockDim.x + threadIdx.x;
    int b = idx >> 8, j = idx & 255;
    size_t r1 = (size_t)b * G1_N;
    size_t r2 = (size_t)b * 512;
    float zr = sigmoidf_(__half2float(g_C1h[r1 + 512 + j]) + g_bias[512 + j]);
    float zi = sigmoidf_(__half2float(g_C1h[r1 + 768 + j]) + g_bias[768 + j]);
    float er = __half2float(g_C2h[r2 + j])
             + __half2float(g_C1h[r1 + 1024 + j]) + g_bias[1024 + j];
    float ei = __half2float(g_C2h[r2 + 256 + j])
             + __half2float(g_C1h[r1 + 1280 + j]) + g_bias[1280 + j];
    float hhr = tanhf(er);
    float hhi = tanhf(ei);
    float hr = h_re[idx], hi = h_im[idx];
    out[idx] = (1.0f - zr) * hr + zi * hi + zr * hhr - zi * hhi;
    out[(size_t)B_ROWS * HDIM + idx] =
        (1.0f - zr) * hi - zi * hr + zr * hhi + zi * hhr;
}

// ---- launch -------------------------------------------------------------------
extern "C" void kernel_launch(void* const* d_in, const int* in_sizes, int n_in,
                              void* d_out, int out_size)
{
    const float* x_re    = (const float*)d_in[0];
    const float* x_im    = (const float*)d_in[1];
    const float* h_re    = (const float*)d_in[2];
    const float* h_im    = (const float*)d_in[3];
    const float* wr_w_re = (const float*)d_in[4];
    const float* wr_w_im = (const float*)d_in[5];
    const float* wr_b_re = (const float*)d_in[6];
    const float* wr_b_im = (const float*)d_in[7];
    const float* wz_w_re = (const float*)d_in[8];
    const float* wz_w_im = (const float*)d_in[9];
    const float* wz_b_re = (const float*)d_in[10];
    const float* wz_b_im = (const float*)d_in[11];
    const float* wh_w_re = (const float*)d_in[12];
    const float* wh_w_im = (const float*)d_in[13];
    const float* wh_b_re = (const float*)d_in[14];
    const float* wh_b_im = (const float*)d_in[15];
    const float* ur_w_re = (const float*)d_in[16];
    const float* ur_w_im = (const float*)d_in[17];
    const float* uz_w_re = (const float*)d_in[18];
    const float* uz_w_im = (const float*)d_in[19];
    const float* uh_w_re = (const float*)d_in[20];
    const float* uh_w_im = (const float*)d_in[21];

    static int smem_set = 0;
    if (!smem_set) {
        cudaFuncSetAttribute(hgemm, cudaFuncAttributeMaxDynamicSharedMemorySize,
                             HG_SMEM);
        smem_set = 1;
    }

    prep_g1<<<(G1_N * G1_K) / 256, 256>>>(wr_w_re, wr_w_im, wz_w_re, wz_w_im,
                                          wh_w_re, wh_w_im, ur_w_re, ur_w_im,
                                          uz_w_re, uz_w_im, uh_w_re, uh_w_im);
    prep_g2<<<(G2_N * G2_K) / 256, 256>>>(wh_w_re, wh_w_im);
    prep_bias<<<G1_N / 256, 256>>>(wr_b_re, wr_b_im, wz_b_re, wz_b_im,
                                   wh_b_re, wh_b_im);
    convA<<<(B_ROWS * 256) / 256, 256>>>(x_re, x_im, h_re, h_im);

    dim3 blk(128);
    dim3 grid1(G1_N / BN, B_ROWS / BM);   // 12 x 128
    hgemm<<<grid1, blk, HG_SMEM>>>(0);

    e1_kernel<<<(B_ROWS * HDIM) / 256, 256>>>(h_re, h_im);

    dim3 grid2(G2_N / BN, B_ROWS / BM);   // 4 x 128
    hgemm<<<grid2, blk, HG_SMEM>>>(1);

    e2_kernel<<<(B_ROWS * HDIM) / 256, 256>>>(h_re, h_im, (float*)d_out);
}